// round 8
// baseline (speedup 1.0000x reference)
#include <cuda_runtime.h>
#include <math.h>

#define DDIM 2048
#define DEPTH 9
#define BM 128
#define BN 128
#define BK 16
#define TM 8
#define TN 8
#define NCHUNK 4
#define CHUNK (DDIM / NCHUNK)   // 512

// Scratch (no allocation allowed) — ping-pong activation buffers + u vectors.
__device__ float g_buf0[(size_t)DDIM * DDIM];
__device__ float g_buf1[(size_t)DDIM * DDIM];
__device__ float g_u1[DDIM];
__device__ float g_u2[DDIM];

// u[j] = (1/n) * (prod_{d,g} cos(uw[d, j, g]))^2   (closed form of _ultimate)
__global__ void ultimate_u_kernel(const float* __restrict__ uw, float* __restrict__ u) {
    int j = blockIdx.x * blockDim.x + threadIdx.x;
    if (j >= DDIM) return;
    float p = 1.0f;
#pragma unroll
    for (int d = 0; d < DEPTH; d++) {
        size_t base = (size_t)d * DDIM * DDIM + (size_t)j * DDIM;
        p *= cosf(uw[base + 0]);
        p *= cosf(uw[base + 1]);
        p *= cosf(uw[base + 2]);
    }
    u[j] = p * p * (1.0f / (float)DDIM);
}

// MODE 0: C = relu(A @ W^T + bias)          W is [N,K] row-major, use W[n,k]
// MODE 1: C = tanh(A @ W + bias + u)        W is [K,N] row-major, use W[k,n]
// Accumulation replicates split-K=4: serial fp32 FMA (increasing k) within each
// contiguous 512-chunk; running sum += chunk partial at each boundary, which
// reproduces ((p0+p1)+p2)+p3 exactly.
template <int MODE>
__global__ __launch_bounds__(256, 1) void gemm_kernel(
    const float* __restrict__ A, const float* __restrict__ W,
    const float* __restrict__ bias, const float* __restrict__ u,
    float* __restrict__ C)
{
    __shared__ float As[BK][BM + 4];
    __shared__ float Bs[BK][BN + 4];

    const int tid = threadIdx.x;
    const int tx = tid & 15;         // 0..15 -> N direction (TN=8 each)
    const int ty = tid >> 4;         // 0..15 -> M direction (TM=8 each)
    const int m0 = blockIdx.y * BM;
    const int n0 = blockIdx.x * BN;

    float sum[TM][TN];               // combined partials (chunk order)
    float acc[TM][TN];               // live chunk accumulator
#pragma unroll
    for (int i = 0; i < TM; i++)
#pragma unroll
        for (int j = 0; j < TN; j++) { sum[i][j] = 0.0f; acc[i][j] = 0.0f; }

    for (int chunk = 0; chunk < NCHUNK; chunk++) {
        const int kbeg = chunk * CHUNK;
        for (int k0 = kbeg; k0 < kbeg + CHUNK; k0 += BK) {
            // ---- load A tile: rows m0..m0+127, cols k0..k0+15, store transposed
#pragma unroll
            for (int it = 0; it < 2; it++) {
                int idx = tid + it * 256;          // 0..511 float4 slots
                int r   = idx >> 2;                // 0..127 row within tile
                int c4  = idx & 3;                 // float4 group along k
                float4 v = *(const float4*)(A + (size_t)(m0 + r) * DDIM + k0 + c4 * 4);
                As[c4 * 4 + 0][r] = v.x;
                As[c4 * 4 + 1][r] = v.y;
                As[c4 * 4 + 2][r] = v.z;
                As[c4 * 4 + 3][r] = v.w;
            }
            // ---- load B tile
            if (MODE == 0) {
                // NT: W[n,k], rows n0..n0+127, cols k0..k0+15 -> transpose into Bs[k][n]
#pragma unroll
                for (int it = 0; it < 2; it++) {
                    int idx = tid + it * 256;
                    int r   = idx >> 2;
                    int c4  = idx & 3;
                    float4 v = *(const float4*)(W + (size_t)(n0 + r) * DDIM + k0 + c4 * 4);
                    Bs[c4 * 4 + 0][r] = v.x;
                    Bs[c4 * 4 + 1][r] = v.y;
                    Bs[c4 * 4 + 2][r] = v.z;
                    Bs[c4 * 4 + 3][r] = v.w;
                }
            } else {
                // NN: W[k,n], rows k0..k0+15, cols n0..n0+127 -> direct copy
#pragma unroll
                for (int it = 0; it < 2; it++) {
                    int idx = tid + it * 256;      // 0..511 float4 slots
                    int r   = idx >> 5;            // 0..15 (k)
                    int c4  = idx & 31;            // 0..31 (float4 group along n)
                    float4 v = *(const float4*)(W + (size_t)(k0 + r) * DDIM + n0 + c4 * 4);
                    *(float4*)&Bs[r][c4 * 4] = v;  // (BN+4)=132 floats/row: 16B-aligned
                }
            }
            __syncthreads();

#pragma unroll
            for (int k = 0; k < BK; k++) {
                float a[TM], b[TN];
#pragma unroll
                for (int i = 0; i < TM; i += 4)
                    *(float4*)&a[i] = *(const float4*)&As[k][ty * TM + i];
#pragma unroll
                for (int j = 0; j < TN; j += 4)
                    *(float4*)&b[j] = *(const float4*)&Bs[k][tx * TN + j];
#pragma unroll
                for (int i = 0; i < TM; i++)
#pragma unroll
                    for (int j = 0; j < TN; j++)
                        acc[i][j] = fmaf(a[i], b[j], acc[i][j]);
            }
            __syncthreads();
        }
        // chunk boundary: fold partial into running sum (preserves combine order)
#pragma unroll
        for (int i = 0; i < TM; i++)
#pragma unroll
            for (int j = 0; j < TN; j++) {
                sum[i][j] = sum[i][j] + acc[i][j];
                acc[i][j] = 0.0f;
            }
    }

    // ---- fused epilogue
#pragma unroll
    for (int i = 0; i < TM; i++) {
        int row = m0 + ty * TM + i;
#pragma unroll
        for (int j = 0; j < TN; j += 4) {
            int col = n0 + tx * TN + j;
            float4 v;
            v.x = sum[i][j + 0] + bias[col + 0];
            v.y = sum[i][j + 1] + bias[col + 1];
            v.z = sum[i][j + 2] + bias[col + 2];
            v.w = sum[i][j + 3] + bias[col + 3];
            if (MODE == 1) {
                v.x = tanhf(v.x + u[col + 0]);
                v.y = tanhf(v.y + u[col + 1]);
                v.z = tanhf(v.z + u[col + 2]);
                v.w = tanhf(v.w + u[col + 3]);
            } else {
                v.x = fmaxf(v.x, 0.0f);
                v.y = fmaxf(v.y, 0.0f);
                v.z = fmaxf(v.z, 0.0f);
                v.w = fmaxf(v.w, 0.0f);
            }
            *(float4*)(C + (size_t)row * DDIM + col) = v;
        }
    }
}

extern "C" void kernel_launch(void* const* d_in, const int* in_sizes, int n_in,
                              void* d_out, int out_size) {
    const float* x   = (const float*)d_in[0];
    const float* w0  = (const float*)d_in[1];
    const float* b0  = (const float*)d_in[2];
    const float* w1  = (const float*)d_in[3];
    const float* b1  = (const float*)d_in[4];
    const float* uw1 = (const float*)d_in[5];
    const float* cw1 = (const float*)d_in[6];
    const float* cb1 = (const float*)d_in[7];
    const float* w2  = (const float*)d_in[8];
    const float* b2  = (const float*)d_in[9];
    const float* uw2 = (const float*)d_in[10];
    const float* cw2 = (const float*)d_in[11];
    const float* cb2 = (const float*)d_in[12];
    const float* wf  = (const float*)d_in[13];
    const float* bf  = (const float*)d_in[14];
    float* out = (float*)d_out;

    float *buf0, *buf1, *u1, *u2;
    cudaGetSymbolAddress((void**)&buf0, g_buf0);
    cudaGetSymbolAddress((void**)&buf1, g_buf1);
    cudaGetSymbolAddress((void**)&u1, g_u1);
    cudaGetSymbolAddress((void**)&u2, g_u2);

    dim3 grid(DDIM / BN, DDIM / BM);
    dim3 block(256);

    // closed-form "quantum" vectors
    ultimate_u_kernel<<<DDIM / 256, 256>>>(uw1, u1);
    ultimate_u_kernel<<<DDIM / 256, 256>>>(uw2, u2);

    // 1) h = relu(x @ w0^T + b0)
    gemm_kernel<0><<<grid, block>>>(x, w0, b0, nullptr, buf0);
    // 2) h = relu(h @ w1^T + b1)
    gemm_kernel<0><<<grid, block>>>(buf0, w1, b1, nullptr, buf1);
    // 3) h = tanh(h @ cw1 + cb1 + u1)
    gemm_kernel<1><<<grid, block>>>(buf1, cw1, cb1, u1, buf0);
    // 4) h = relu(h @ w2^T + b2)
    gemm_kernel<0><<<grid, block>>>(buf0, w2, b2, nullptr, buf1);
    // 5) h = tanh(h @ cw2 + cb2 + u2)
    gemm_kernel<1><<<grid, block>>>(buf1, cw2, cb2, u2, buf0);
    // 6) out = relu(h @ wf^T + bf)
    gemm_kernel<0><<<grid, block>>>(buf0, wf, bf, nullptr, out);
}

// round 9
// speedup vs baseline: 1.0284x; 1.0284x over previous
#include <cuda_runtime.h>
#include <math.h>

#define DDIM 2048
#define DEPTH 9
#define BM 128
#define BN 128
#define BK 16
#define TM 8
#define TN 8
#define NCHUNK 4
#define CHUNK (DDIM / NCHUNK)   // 512

typedef unsigned long long u64;

// Packed fp32x2 ops (Blackwell FFMA2 path). Each 32-bit lane gets IEEE fp32 .rn
// rounding identical to scalar fmaf/add — bit-exact per element.
#define FMA_F32X2(d, a, b, c) \
    asm("fma.rn.f32x2 %0, %1, %2, %3;" : "=l"(d) : "l"(a), "l"(b), "l"(c))
#define ADD_F32X2_(d, a, b) \
    asm("add.rn.f32x2 %0, %1, %2;" : "=l"(d) : "l"(a), "l"(b))
#define PACK_F32X2_(out, lo, hi) \
    asm("mov.b64 %0, {%1, %2};" : "=l"(out) : "f"(lo), "f"(hi))
#define UNPACK_F32X2_(lo, hi, in) \
    asm("mov.b64 {%0, %1}, %2;" : "=f"(lo), "=f"(hi) : "l"(in))

// Scratch (no allocation allowed) — ping-pong activation buffers + u vectors.
__device__ float g_buf0[(size_t)DDIM * DDIM];
__device__ float g_buf1[(size_t)DDIM * DDIM];
__device__ float g_u1[DDIM];
__device__ float g_u2[DDIM];

// u[j] = (1/n) * (prod_{d,g} cos(uw[d, j, g]))^2   (closed form of _ultimate)
__global__ void ultimate_u_kernel(const float* __restrict__ uw, float* __restrict__ u) {
    int j = blockIdx.x * blockDim.x + threadIdx.x;
    if (j >= DDIM) return;
    float p = 1.0f;
#pragma unroll
    for (int d = 0; d < DEPTH; d++) {
        size_t base = (size_t)d * DDIM * DDIM + (size_t)j * DDIM;
        p *= cosf(uw[base + 0]);
        p *= cosf(uw[base + 1]);
        p *= cosf(uw[base + 2]);
    }
    u[j] = p * p * (1.0f / (float)DDIM);
}

// MODE 0: C = relu(A @ W^T + bias)          W is [N,K] row-major
// MODE 1: C = tanh(A @ W + bias + u)        W is [K,N] row-major
// Accumulation replicates split-K=4: serial fp32 FMA (increasing k) within each
// contiguous 512-chunk; partials combined in chunk order. f32x2 packs two output
// columns per instruction; each element's rounding chain is unchanged.
template <int MODE>
__global__ __launch_bounds__(256, 1) void gemm_kernel(
    const float* __restrict__ A, const float* __restrict__ W,
    const float* __restrict__ bias, const float* __restrict__ u,
    float* __restrict__ C)
{
    __shared__ float As[BK][BM + 4];
    __shared__ float Bs[BK][BN + 4];

    const int tid = threadIdx.x;
    const int tx = tid & 15;         // 0..15 -> N direction (TN=8 each)
    const int ty = tid >> 4;         // 0..15 -> M direction (TM=8 each)
    const int m0 = blockIdx.y * BM;
    const int n0 = blockIdx.x * BN;

    u64 sum2[TM][TN / 2];            // combined partials (chunk order), packed pairs
    u64 acc2[TM][TN / 2];            // live chunk accumulator, packed pairs
#pragma unroll
    for (int i = 0; i < TM; i++)
#pragma unroll
        for (int jp = 0; jp < TN / 2; jp++) { sum2[i][jp] = 0ULL; acc2[i][jp] = 0ULL; }

    for (int chunk = 0; chunk < NCHUNK; chunk++) {
        const int kbeg = chunk * CHUNK;
        for (int k0 = kbeg; k0 < kbeg + CHUNK; k0 += BK) {
            // ---- load A tile: rows m0..m0+127, cols k0..k0+15, store transposed
#pragma unroll
            for (int it = 0; it < 2; it++) {
                int idx = tid + it * 256;          // 0..511 float4 slots
                int r   = idx >> 2;                // 0..127 row within tile
                int c4  = idx & 3;                 // float4 group along k
                float4 v = *(const float4*)(A + (size_t)(m0 + r) * DDIM + k0 + c4 * 4);
                As[c4 * 4 + 0][r] = v.x;
                As[c4 * 4 + 1][r] = v.y;
                As[c4 * 4 + 2][r] = v.z;
                As[c4 * 4 + 3][r] = v.w;
            }
            // ---- load B tile
            if (MODE == 0) {
                // NT: W[n,k] -> transpose into Bs[k][n]
#pragma unroll
                for (int it = 0; it < 2; it++) {
                    int idx = tid + it * 256;
                    int r   = idx >> 2;
                    int c4  = idx & 3;
                    float4 v = *(const float4*)(W + (size_t)(n0 + r) * DDIM + k0 + c4 * 4);
                    Bs[c4 * 4 + 0][r] = v.x;
                    Bs[c4 * 4 + 1][r] = v.y;
                    Bs[c4 * 4 + 2][r] = v.z;
                    Bs[c4 * 4 + 3][r] = v.w;
                }
            } else {
                // NN: W[k,n] -> direct copy
#pragma unroll
                for (int it = 0; it < 2; it++) {
                    int idx = tid + it * 256;      // 0..511 float4 slots
                    int r   = idx >> 5;            // 0..15 (k)
                    int c4  = idx & 31;            // 0..31 (float4 group along n)
                    float4 v = *(const float4*)(W + (size_t)(k0 + r) * DDIM + n0 + c4 * 4);
                    *(float4*)&Bs[r][c4 * 4] = v;  // (BN+4)=132 floats/row: 16B-aligned
                }
            }
            __syncthreads();

#pragma unroll
            for (int k = 0; k < BK; k++) {
                float a[TM];
                u64 a2[TM], b2[TN / 2];
#pragma unroll
                for (int i = 0; i < TM; i += 4)
                    *(float4*)&a[i] = *(const float4*)&As[k][ty * TM + i];
#pragma unroll
                for (int i = 0; i < TM; i++)
                    PACK_F32X2_(a2[i], a[i], a[i]);
                // b pairs load directly as packed 64-bit lanes (16B-aligned)
                *(ulonglong2*)&b2[0] = *(const ulonglong2*)&Bs[k][tx * TN];
                *(ulonglong2*)&b2[2] = *(const ulonglong2*)&Bs[k][tx * TN + 4];
#pragma unroll
                for (int i = 0; i < TM; i++)
#pragma unroll
                    for (int jp = 0; jp < TN / 2; jp++)
                        FMA_F32X2(acc2[i][jp], a2[i], b2[jp], acc2[i][jp]);
            }
            __syncthreads();
        }
        // chunk boundary: fold partial into running sum (preserves combine order)
#pragma unroll
        for (int i = 0; i < TM; i++)
#pragma unroll
            for (int jp = 0; jp < TN / 2; jp++) {
                ADD_F32X2_(sum2[i][jp], sum2[i][jp], acc2[i][jp]);
                acc2[i][jp] = 0ULL;
            }
    }

    // ---- fused epilogue
#pragma unroll
    for (int i = 0; i < TM; i++) {
        int row = m0 + ty * TM + i;
#pragma unroll
        for (int j = 0; j < TN; j += 4) {
            int col = n0 + tx * TN + j;
            float s0, s1, s2, s3;
            UNPACK_F32X2_(s0, s1, sum2[i][j / 2]);
            UNPACK_F32X2_(s2, s3, sum2[i][j / 2 + 1]);
            float4 v;
            v.x = s0 + bias[col + 0];
            v.y = s1 + bias[col + 1];
            v.z = s2 + bias[col + 2];
            v.w = s3 + bias[col + 3];
            if (MODE == 1) {
                v.x = tanhf(v.x + u[col + 0]);
                v.y = tanhf(v.y + u[col + 1]);
                v.z = tanhf(v.z + u[col + 2]);
                v.w = tanhf(v.w + u[col + 3]);
            } else {
                v.x = fmaxf(v.x, 0.0f);
                v.y = fmaxf(v.y, 0.0f);
                v.z = fmaxf(v.z, 0.0f);
                v.w = fmaxf(v.w, 0.0f);
            }
            *(float4*)(C + (size_t)row * DDIM + col) = v;
        }
    }
}

extern "C" void kernel_launch(void* const* d_in, const int* in_sizes, int n_in,
                              void* d_out, int out_size) {
    const float* x   = (const float*)d_in[0];
    const float* w0  = (const float*)d_in[1];
    const float* b0  = (const float*)d_in[2];
    const float* w1  = (const float*)d_in[3];
    const float* b1  = (const float*)d_in[4];
    const float* uw1 = (const float*)d_in[5];
    const float* cw1 = (const float*)d_in[6];
    const float* cb1 = (const float*)d_in[7];
    const float* w2  = (const float*)d_in[8];
    const float* b2  = (const float*)d_in[9];
    const float* uw2 = (const float*)d_in[10];
    const float* cw2 = (const float*)d_in[11];
    const float* cb2 = (const float*)d_in[12];
    const float* wf  = (const float*)d_in[13];
    const float* bf  = (const float*)d_in[14];
    float* out = (float*)d_out;

    float *buf0, *buf1, *u1, *u2;
    cudaGetSymbolAddress((void**)&buf0, g_buf0);
    cudaGetSymbolAddress((void**)&buf1, g_buf1);
    cudaGetSymbolAddress((void**)&u1, g_u1);
    cudaGetSymbolAddress((void**)&u2, g_u2);

    dim3 grid(DDIM / BN, DDIM / BM);
    dim3 block(256);

    // closed-form "quantum" vectors
    ultimate_u_kernel<<<DDIM / 256, 256>>>(uw1, u1);
    ultimate_u_kernel<<<DDIM / 256, 256>>>(uw2, u2);

    // 1) h = relu(x @ w0^T + b0)
    gemm_kernel<0><<<grid, block>>>(x, w0, b0, nullptr, buf0);
    // 2) h = relu(h @ w1^T + b1)
    gemm_kernel<0><<<grid, block>>>(buf0, w1, b1, nullptr, buf1);
    // 3) h = tanh(h @ cw1 + cb1 + u1)
    gemm_kernel<1><<<grid, block>>>(buf1, cw1, cb1, u1, buf0);
    // 4) h = relu(h @ w2^T + b2)
    gemm_kernel<0><<<grid, block>>>(buf0, w2, b2, nullptr, buf1);
    // 5) h = tanh(h @ cw2 + cb2 + u2)
    gemm_kernel<1><<<grid, block>>>(buf1, cw2, cb2, u2, buf0);
    // 6) out = relu(h @ wf^T + bf)
    gemm_kernel<0><<<grid, block>>>(buf0, wf, bf, nullptr, out);
}